// round 1
// baseline (speedup 1.0000x reference)
#include <cuda_runtime.h>

#define NN   50000
#define EE   800000
#define EPAD 850000   // E + N self loops
#define IN1  192
#define C1   256

// ---------------- scratch (device globals; no runtime allocation) ----------------
__device__ float g_x  [NN * IN1];   // concat(high, elu(emb))
__device__ float g_h1 [NN * C1];    // layer-1 pre-aggregation features
__device__ float g_as1[NN * 8];
__device__ float g_ad1[NN * 8];
__device__ float g_h2 [NN * 8];     // layer-2 features
__device__ float g_a2s[NN];
__device__ float g_a2d[NN];
__device__ int   g_cnt[NN];         // degree counts, then scatter cursor
__device__ int   g_off[NN + 1];     // CSR offsets (by destination)
__device__ int   g_csr[EPAD];       // source index per CSR slot

// ---------------- kernel 0: emb = elu(low@W_emb + b), x = [high | emb] ----------------
__global__ void k_emb(const float* __restrict__ high, const float* __restrict__ low,
                      const float* __restrict__ Wemb, const float* __restrict__ bemb) {
    __shared__ float ls[2][32];
    int n = blockIdx.x * 2 + threadIdx.y;
    int c = threadIdx.x;
    if (c < 32) ls[threadIdx.y][c] = low[n * 32 + c];
    __syncthreads();
    if (c < 128) {
        g_x[n * IN1 + c] = high[n * 128 + c];
    } else {
        int j = c - 128;
        float s = bemb[j];
#pragma unroll
        for (int k = 0; k < 32; k++) s += ls[threadIdx.y][k] * Wemb[k * 64 + j];
        g_x[n * IN1 + c] = s > 0.f ? s : expm1f(s);
    }
}

// ---------------- kernel 1: h1 = x @ W1   ([50000,192] x [192,256]) ----------------
__global__ void __launch_bounds__(256) k_gemm(const float* __restrict__ W1) {
    __shared__ float As[16][128];
    __shared__ float Bs[16][64];
    int bm = blockIdx.x * 128, bn = blockIdx.y * 64;
    int tid = threadIdx.x;
    int tx = tid & 15, ty = tid >> 4;
    float acc[8][4];
#pragma unroll
    for (int i = 0; i < 8; i++)
#pragma unroll
        for (int j = 0; j < 4; j++) acc[i][j] = 0.f;

    for (int k0 = 0; k0 < IN1; k0 += 16) {
#pragma unroll
        for (int it = 0; it < 2; it++) {
            int idx = tid + it * 256;          // 0..511
            int r = idx >> 2, c4 = idx & 3;    // row 0..127, float4 col 0..3
            float4 v = make_float4(0.f, 0.f, 0.f, 0.f);
            int m = bm + r;
            if (m < NN) v = *(const float4*)&g_x[m * IN1 + k0 + c4 * 4];
            As[c4 * 4 + 0][r] = v.x; As[c4 * 4 + 1][r] = v.y;
            As[c4 * 4 + 2][r] = v.z; As[c4 * 4 + 3][r] = v.w;
        }
        {
            int r = tid >> 4, c4 = tid & 15;
            float4 v = *(const float4*)&W1[(k0 + r) * C1 + bn + c4 * 4];
            *(float4*)&Bs[r][c4 * 4] = v;
        }
        __syncthreads();
#pragma unroll
        for (int k = 0; k < 16; k++) {
            float4 a0 = *(const float4*)&As[k][ty * 8];
            float4 a1 = *(const float4*)&As[k][ty * 8 + 4];
            float4 b  = *(const float4*)&Bs[k][tx * 4];
            float a[8] = {a0.x, a0.y, a0.z, a0.w, a1.x, a1.y, a1.z, a1.w};
            float bb[4] = {b.x, b.y, b.z, b.w};
#pragma unroll
            for (int i = 0; i < 8; i++)
#pragma unroll
                for (int j = 0; j < 4; j++) acc[i][j] += a[i] * bb[j];
        }
        __syncthreads();
    }
#pragma unroll
    for (int i = 0; i < 8; i++) {
        int m = bm + ty * 8 + i;
        if (m < NN)
            *(float4*)&g_h1[m * C1 + bn + tx * 4] =
                make_float4(acc[i][0], acc[i][1], acc[i][2], acc[i][3]);
    }
}

// ---------------- kernel 2: per-node attention logits (layer 1) ----------------
__global__ void k_att1(const float* __restrict__ a_s, const float* __restrict__ a_d) {
    int n = blockIdx.x * 8 + (threadIdx.x >> 5);
    int lane = threadIdx.x & 31;
    if (n >= NN) return;
#pragma unroll
    for (int h = 0; h < 8; h++) {
        float x = g_h1[n * C1 + h * 32 + lane];
        float s = x * a_s[h * 32 + lane];
        float d = x * a_d[h * 32 + lane];
#pragma unroll
        for (int o = 16; o > 0; o >>= 1) {
            s += __shfl_xor_sync(~0u, s, o);
            d += __shfl_xor_sync(~0u, d, o);
        }
        if (lane == 0) { g_as1[n * 8 + h] = s; g_ad1[n * 8 + h] = d; }
    }
}

// ---------------- CSR build ----------------
__global__ void k_cnt_init() {
    int i = blockIdx.x * blockDim.x + threadIdx.x;
    if (i < NN) g_cnt[i] = 1;   // self loop
}
__global__ void k_cnt_edges(const int* __restrict__ ei) {
    int e = blockIdx.x * blockDim.x + threadIdx.x;
    if (e < EE) atomicAdd(&g_cnt[ei[EE + e]], 1);
}
__global__ void k_scan() {
    __shared__ int sums[1024];
    int t = threadIdx.x;
    const int CH = (NN + 1023) / 1024;   // 49
    int base = t * CH;
    int s = 0;
    for (int i = 0; i < CH; i++) { int idx = base + i; if (idx < NN) s += g_cnt[idx]; }
    sums[t] = s;
    __syncthreads();
    for (int off = 1; off < 1024; off <<= 1) {
        int v = (t >= off) ? sums[t - off] : 0;
        __syncthreads();
        sums[t] += v;
        __syncthreads();
    }
    int run = sums[t] - s;    // exclusive prefix for this chunk
    for (int i = 0; i < CH; i++) {
        int idx = base + i;
        if (idx < NN) { g_off[idx] = run; run += g_cnt[idx]; }
    }
    if (t == 1023) g_off[NN] = sums[1023];
}
__global__ void k_selfloop() {
    int i = blockIdx.x * blockDim.x + threadIdx.x;
    if (i < NN) { int o = g_off[i]; g_csr[o] = i; g_cnt[i] = o + 1; }
}
__global__ void k_scatter(const int* __restrict__ ei) {
    int e = blockIdx.x * blockDim.x + threadIdx.x;
    if (e < EE) {
        int s = ei[e], d = ei[EE + e];
        int p = atomicAdd(&g_cnt[d], 1);
        g_csr[p] = s;
    }
}

// ---------------- kernel 4: layer-1 aggregation + elu + fused layer-2 prep ----------------
__global__ void __launch_bounds__(256) k_agg1(const float* __restrict__ b1,
                                              const float* __restrict__ W2,
                                              const float* __restrict__ as2,
                                              const float* __restrict__ ad2) {
    int d = (blockIdx.x * blockDim.x + threadIdx.x) >> 5;
    int lane = threadIdx.x & 31;
    if (d >= NN) return;
    int beg = g_off[d], end = g_off[d + 1];

    float ad[8];
#pragma unroll
    for (int h = 0; h < 8; h++) ad[h] = g_ad1[d * 8 + h];

    // pass 1: per-head running max over incoming edges (lane-parallel)
    float mh[8];
#pragma unroll
    for (int h = 0; h < 8; h++) mh[h] = -1e30f;
    for (int e = beg + lane; e < end; e += 32) {
        int s = g_csr[e];
        const float4* ap = (const float4*)&g_as1[s * 8];
        float4 a0 = ap[0], a1 = ap[1];
        float av[8] = {a0.x, a0.y, a0.z, a0.w, a1.x, a1.y, a1.z, a1.w};
#pragma unroll
        for (int h = 0; h < 8; h++) {
            float a = av[h] + ad[h];
            a = a > 0.f ? a : 0.2f * a;
            mh[h] = fmaxf(mh[h], a);
        }
    }
    float m_me = 0.f, ad_me = 0.f;
#pragma unroll
    for (int h = 0; h < 8; h++) {
        float t = mh[h];
#pragma unroll
        for (int o = 16; o > 0; o >>= 1) t = fmaxf(t, __shfl_xor_sync(~0u, t, o));
        if (lane == h) { m_me = t; ad_me = ad[h]; }
    }

    // pass 2: warp-per-edge accumulate. out = (sum ea*h[src]) / (sum ea)
    int h0 = lane >> 3;
    float4 accA = make_float4(0.f, 0.f, 0.f, 0.f);
    float4 accB = make_float4(0.f, 0.f, 0.f, 0.f);
    float z = 0.f;
    for (int e = beg; e < end; e++) {
        int s = g_csr[e];
        float ea = 0.f;
        if (lane < 8) {
            float a = g_as1[s * 8 + lane] + ad_me;
            a = a > 0.f ? a : 0.2f * a;
            ea = __expf(a - m_me);
            z += ea;
        }
        float eaA = __shfl_sync(~0u, ea, h0);
        float eaB = __shfl_sync(~0u, ea, 4 + h0);
        const float4* hp = (const float4*)&g_h1[s * C1];
        float4 vA = hp[lane];
        float4 vB = hp[32 + lane];
        accA.x += eaA * vA.x; accA.y += eaA * vA.y; accA.z += eaA * vA.z; accA.w += eaA * vA.w;
        accB.x += eaB * vB.x; accB.y += eaB * vB.y; accB.z += eaB * vB.z; accB.w += eaB * vB.w;
    }
    float zA = __shfl_sync(~0u, z, h0) + 1e-16f;
    float zB = __shfl_sync(~0u, z, 4 + h0) + 1e-16f;
    float4 b1A = *(const float4*)&b1[lane * 4];
    float4 b1B = *(const float4*)&b1[128 + lane * 4];

    float xa[4], xb[4];
    xa[0] = accA.x / zA + b1A.x; xa[1] = accA.y / zA + b1A.y;
    xa[2] = accA.z / zA + b1A.z; xa[3] = accA.w / zA + b1A.w;
    xb[0] = accB.x / zB + b1B.x; xb[1] = accB.y / zB + b1B.y;
    xb[2] = accB.z / zB + b1B.z; xb[3] = accB.w / zB + b1B.w;
#pragma unroll
    for (int j = 0; j < 4; j++) {
        xa[j] = xa[j] > 0.f ? xa[j] : expm1f(xa[j]);
        xb[j] = xb[j] > 0.f ? xb[j] : expm1f(xb[j]);
    }

    // fused layer-2: h2 = x1 @ W2 (x1 row lives across the warp: lane owns flats lane*4.. and 128+lane*4..)
    float p[8];
#pragma unroll
    for (int o = 0; o < 8; o++) p[o] = 0.f;
#pragma unroll
    for (int j = 0; j < 4; j++) {
        const float4* wA = (const float4*)&W2[(lane * 4 + j) * 8];
        const float4* wB = (const float4*)&W2[(128 + lane * 4 + j) * 8];
        float4 w0 = wA[0], w1 = wA[1], u0 = wB[0], u1 = wB[1];
        p[0] += xa[j] * w0.x + xb[j] * u0.x;
        p[1] += xa[j] * w0.y + xb[j] * u0.y;
        p[2] += xa[j] * w0.z + xb[j] * u0.z;
        p[3] += xa[j] * w0.w + xb[j] * u0.w;
        p[4] += xa[j] * w1.x + xb[j] * u1.x;
        p[5] += xa[j] * w1.y + xb[j] * u1.y;
        p[6] += xa[j] * w1.z + xb[j] * u1.z;
        p[7] += xa[j] * w1.w + xb[j] * u1.w;
    }
#pragma unroll
    for (int o = 0; o < 8; o++)
#pragma unroll
        for (int k = 16; k > 0; k >>= 1) p[o] += __shfl_xor_sync(~0u, p[o], k);

    float s2 = 0.f, d2 = 0.f;
#pragma unroll
    for (int o = 0; o < 8; o++) { s2 += p[o] * as2[o]; d2 += p[o] * ad2[o]; }
    if (lane == 0) {
        g_a2s[d] = s2; g_a2d[d] = d2;
        *(float4*)&g_h2[d * 8]     = make_float4(p[0], p[1], p[2], p[3]);
        *(float4*)&g_h2[d * 8 + 4] = make_float4(p[4], p[5], p[6], p[7]);
    }
}

// ---------------- kernel 5: layer-2 aggregation + log_softmax ----------------
__global__ void __launch_bounds__(256) k_agg2(const float* __restrict__ b2,
                                              float* __restrict__ out) {
    int d = (blockIdx.x * blockDim.x + threadIdx.x) >> 5;
    int lane = threadIdx.x & 31;
    if (d >= NN) return;
    int beg = g_off[d], end = g_off[d + 1];
    float adv = g_a2d[d];

    float mloc = -1e30f;
    for (int e = beg + lane; e < end; e += 32) {
        int s = g_csr[e];
        float a = g_a2s[s] + adv;
        a = a > 0.f ? a : 0.2f * a;
        mloc = fmaxf(mloc, a);
    }
#pragma unroll
    for (int o = 16; o > 0; o >>= 1) mloc = fmaxf(mloc, __shfl_xor_sync(~0u, mloc, o));

    float z = 0.f, acc[8];
#pragma unroll
    for (int o = 0; o < 8; o++) acc[o] = 0.f;
    for (int e = beg + lane; e < end; e += 32) {
        int s = g_csr[e];
        float a = g_a2s[s] + adv;
        a = a > 0.f ? a : 0.2f * a;
        float ea = __expf(a - mloc);
        z += ea;
        const float4* hp = (const float4*)&g_h2[s * 8];
        float4 v0 = hp[0], v1 = hp[1];
        acc[0] += ea * v0.x; acc[1] += ea * v0.y; acc[2] += ea * v0.z; acc[3] += ea * v0.w;
        acc[4] += ea * v1.x; acc[5] += ea * v1.y; acc[6] += ea * v1.z; acc[7] += ea * v1.w;
    }
#pragma unroll
    for (int k = 16; k > 0; k >>= 1) z += __shfl_xor_sync(~0u, z, k);
#pragma unroll
    for (int o = 0; o < 8; o++)
#pragma unroll
        for (int k = 16; k > 0; k >>= 1) acc[o] += __shfl_xor_sync(~0u, acc[o], k);

    float inv = 1.f / (z + 1e-16f);
    float v[8], mx = -1e30f;
#pragma unroll
    for (int o = 0; o < 8; o++) { v[o] = acc[o] * inv + b2[o]; mx = fmaxf(mx, v[o]); }
    float se = 0.f;
#pragma unroll
    for (int o = 0; o < 8; o++) se += expf(v[o] - mx);
    float lse = mx + logf(se);
    if (lane == 0) {
        *(float4*)&out[d * 8]     = make_float4(v[0] - lse, v[1] - lse, v[2] - lse, v[3] - lse);
        *(float4*)&out[d * 8 + 4] = make_float4(v[4] - lse, v[5] - lse, v[6] - lse, v[7] - lse);
    }
}

// ---------------- launch ----------------
extern "C" void kernel_launch(void* const* d_in, const int* in_sizes, int n_in,
                              void* d_out, int out_size) {
    const float* high  = (const float*)d_in[0];
    const float* low   = (const float*)d_in[1];
    const int*   ei    = (const int*)d_in[2];
    const float* Wemb  = (const float*)d_in[3];
    const float* bemb  = (const float*)d_in[4];
    const float* W1    = (const float*)d_in[5];
    const float* asrc1 = (const float*)d_in[6];
    const float* adst1 = (const float*)d_in[7];
    const float* b1    = (const float*)d_in[8];
    const float* W2    = (const float*)d_in[9];
    const float* as2   = (const float*)d_in[10];
    const float* ad2   = (const float*)d_in[11];
    const float* b2    = (const float*)d_in[12];
    float* out = (float*)d_out;

    // CSR build (independent of feature pipeline, but single stream anyway)
    k_cnt_init<<<(NN + 255) / 256, 256>>>();
    k_cnt_edges<<<(EE + 255) / 256, 256>>>(ei);
    k_scan<<<1, 1024>>>();
    k_selfloop<<<(NN + 255) / 256, 256>>>();
    k_scatter<<<(EE + 255) / 256, 256>>>(ei);

    dim3 eb(192, 2);
    k_emb<<<NN / 2, eb>>>(high, low, Wemb, bemb);

    dim3 gg((NN + 127) / 128, C1 / 64);
    k_gemm<<<gg, 256>>>(W1);

    k_att1<<<(NN + 7) / 8, 256>>>(asrc1, adst1);

    k_agg1<<<(NN + 7) / 8, 256>>>(b1, W2, as2, ad2);
    k_agg2<<<(NN + 7) / 8, 256>>>(b2, out);
}

// round 2
// speedup vs baseline: 1.0775x; 1.0775x over previous
#include <cuda_runtime.h>
#include <cuda_fp16.h>

#define NN   50000
#define EE   800000
#define EPAD 850000   // E + N self loops
#define IN1  192
#define C1   256

// ---------------- scratch (device globals; no runtime allocation) ----------------
__device__ float  g_x  [NN * IN1];   // concat(high, elu(emb))
__device__ __half g_h1h[NN * C1];    // layer-1 pre-aggregation features (fp16)
__device__ float  g_as1[NN * 8];
__device__ float  g_ad1[NN * 8];
__device__ float  g_h2 [NN * 8];     // layer-2 features
__device__ float  g_a2s[NN];
__device__ float  g_a2d[NN];
__device__ int    g_cnt[NN];         // degree counts, then scatter cursor
__device__ int    g_off[NN + 1];     // CSR offsets (by destination)
__device__ int    g_csr[EPAD];       // source index per CSR slot

__device__ __forceinline__ unsigned long long dup_f32(float f) {
    unsigned int u = __float_as_uint(f);
    return ((unsigned long long)u << 32) | (unsigned long long)u;
}

// ---------------- kernel 0: emb = elu(low@W_emb + b), x = [high | emb] ----------------
__global__ void k_emb(const float* __restrict__ high, const float* __restrict__ low,
                      const float* __restrict__ Wemb, const float* __restrict__ bemb) {
    __shared__ float ls[2][32];
    int n = blockIdx.x * 2 + threadIdx.y;
    int c = threadIdx.x;
    if (c < 32) ls[threadIdx.y][c] = low[n * 32 + c];
    __syncthreads();
    if (c < 128) {
        g_x[n * IN1 + c] = high[n * 128 + c];
    } else {
        int j = c - 128;
        float s = bemb[j];
#pragma unroll
        for (int k = 0; k < 32; k++) s += ls[threadIdx.y][k] * Wemb[k * 64 + j];
        g_x[n * IN1 + c] = s > 0.f ? s : expm1f(s);
    }
}

// ---------------- kernel 1: h1 = x @ W1  ([50000,192] x [192,256]) with FFMA2 ----------------
// 128x128 tile, 128 threads, each thread 16 rows x 8 cols. Accumulators are
// packed f32x2 row-pairs; B is stored DUPLICATED in shared so the broadcast
// operand of fma.rn.f32x2 needs no register packing.
__global__ void __launch_bounds__(128) k_gemm(const float* __restrict__ W1) {
    __shared__ float As[16][128];                       // [k][m]
    __shared__ unsigned long long Bs2[16][8][16];       // [k][j][tx] duplicated pairs
    int bm = blockIdx.x * 128, bn = blockIdx.y * 128;
    int tid = threadIdx.x;
    int tx = tid & 15, ty = tid >> 4;                   // tx: col group (8 cols), ty: row group (16 rows)

    unsigned long long acc2[8][8];                      // [row-pair][col]
#pragma unroll
    for (int i = 0; i < 8; i++)
#pragma unroll
        for (int j = 0; j < 8; j++) acc2[i][j] = 0ull;

    for (int k0 = 0; k0 < IN1; k0 += 16) {
        // A fill: 128 rows x 16 k, transposed into As[k][m]
#pragma unroll
        for (int it = 0; it < 4; it++) {
            int idx = tid + it * 128;                   // 0..511
            int r = idx >> 2, c4 = idx & 3;
            int m = bm + r;
            float4 v = make_float4(0.f, 0.f, 0.f, 0.f);
            if (m < NN) v = *(const float4*)&g_x[m * IN1 + k0 + c4 * 4];
            As[c4 * 4 + 0][r] = v.x; As[c4 * 4 + 1][r] = v.y;
            As[c4 * 4 + 2][r] = v.z; As[c4 * 4 + 3][r] = v.w;
        }
        // B fill (duplicated): 16 k x 128 cols
#pragma unroll
        for (int it = 0; it < 4; it++) {
            int idx = tid + it * 128;                   // 0..511
            int r = idx >> 5, c4 = idx & 31;            // r: k row, c4: col group of 4
            float4 v = *(const float4*)&W1[(k0 + r) * C1 + bn + c4 * 4];
            int c = c4 * 4;
            Bs2[r][(c + 0) & 7][(c + 0) >> 3] = dup_f32(v.x);
            Bs2[r][(c + 1) & 7][(c + 1) >> 3] = dup_f32(v.y);
            Bs2[r][(c + 2) & 7][(c + 2) >> 3] = dup_f32(v.z);
            Bs2[r][(c + 3) & 7][(c + 3) >> 3] = dup_f32(v.w);
        }
        __syncthreads();
#pragma unroll
        for (int k = 0; k < 16; k++) {
            unsigned long long av[8];
            {
                ulonglong2 t0 = *(const ulonglong2*)&As[k][ty * 16 + 0];
                ulonglong2 t1 = *(const ulonglong2*)&As[k][ty * 16 + 4];
                ulonglong2 t2 = *(const ulonglong2*)&As[k][ty * 16 + 8];
                ulonglong2 t3 = *(const ulonglong2*)&As[k][ty * 16 + 12];
                av[0] = t0.x; av[1] = t0.y; av[2] = t1.x; av[3] = t1.y;
                av[4] = t2.x; av[5] = t2.y; av[6] = t3.x; av[7] = t3.y;
            }
            unsigned long long bv[8];
#pragma unroll
            for (int j = 0; j < 8; j++) bv[j] = Bs2[k][j][tx];
#pragma unroll
            for (int i = 0; i < 8; i++)
#pragma unroll
                for (int j = 0; j < 8; j++)
                    asm("fma.rn.f32x2 %0, %1, %2, %0;"
                        : "+l"(acc2[i][j]) : "l"(av[i]), "l"(bv[j]));
        }
        __syncthreads();
    }
    // epilogue: fp16 store (row-pair unpack)
#pragma unroll
    for (int i = 0; i < 8; i++) {
        int m0 = bm + ty * 16 + 2 * i;
        if (m0 >= NN) continue;
        __half2 hlo[4], hhi[4];
#pragma unroll
        for (int jj = 0; jj < 4; jj++) {
            float2 a0 = *(float2*)&acc2[i][2 * jj];
            float2 a1 = *(float2*)&acc2[i][2 * jj + 1];
            hlo[jj] = __floats2half2_rn(a0.x, a1.x);   // even row
            hhi[jj] = __floats2half2_rn(a0.y, a1.y);   // odd row
        }
        *(uint4*)&g_h1h[(size_t)m0 * C1 + bn + tx * 8] = *(uint4*)hlo;
        if (m0 + 1 < NN)
            *(uint4*)&g_h1h[(size_t)(m0 + 1) * C1 + bn + tx * 8] = *(uint4*)hhi;
    }
}

// ---------------- kernel 2: per-node attention logits (layer 1) ----------------
// warp per node; lane covers 8 cols (one quarter of a head); quad-reduce.
__global__ void k_att1(const float* __restrict__ a_s, const float* __restrict__ a_d) {
    int n = blockIdx.x * 8 + (threadIdx.x >> 5);
    int lane = threadIdx.x & 31;
    if (n >= NN) return;
    uint4 hv = *(const uint4*)&g_h1h[(size_t)n * C1 + lane * 8];
    __half2* hh = (__half2*)&hv;
    int head = lane >> 2;
    int cbase = (lane & 3) * 8;
    float s = 0.f, d = 0.f;
#pragma unroll
    for (int q = 0; q < 4; q++) {
        float2 f = __half22float2(hh[q]);
        s += f.x * a_s[head * 32 + cbase + 2 * q]     + f.y * a_s[head * 32 + cbase + 2 * q + 1];
        d += f.x * a_d[head * 32 + cbase + 2 * q]     + f.y * a_d[head * 32 + cbase + 2 * q + 1];
    }
#pragma unroll
    for (int o = 1; o < 4; o <<= 1) {
        s += __shfl_xor_sync(~0u, s, o);
        d += __shfl_xor_sync(~0u, d, o);
    }
    if ((lane & 3) == 0) { g_as1[n * 8 + head] = s; g_ad1[n * 8 + head] = d; }
}

// ---------------- CSR build ----------------
__global__ void k_cnt_init() {
    int i = blockIdx.x * blockDim.x + threadIdx.x;
    if (i < NN) g_cnt[i] = 1;   // self loop
}
__global__ void k_cnt_edges(const int* __restrict__ ei) {
    int e = blockIdx.x * blockDim.x + threadIdx.x;
    if (e < EE) atomicAdd(&g_cnt[ei[EE + e]], 1);
}
__global__ void k_scan() {
    __shared__ int sums[1024];
    int t = threadIdx.x;
    const int CH = (NN + 1023) / 1024;
    int base = t * CH;
    int s = 0;
    for (int i = 0; i < CH; i++) { int idx = base + i; if (idx < NN) s += g_cnt[idx]; }
    sums[t] = s;
    __syncthreads();
    for (int off = 1; off < 1024; off <<= 1) {
        int v = (t >= off) ? sums[t - off] : 0;
        __syncthreads();
        sums[t] += v;
        __syncthreads();
    }
    int run = sums[t] - s;
    for (int i = 0; i < CH; i++) {
        int idx = base + i;
        if (idx < NN) { g_off[idx] = run; run += g_cnt[idx]; }
    }
    if (t == 1023) g_off[NN] = sums[1023];
}
__global__ void k_selfloop() {
    int i = blockIdx.x * blockDim.x + threadIdx.x;
    if (i < NN) { int o = g_off[i]; g_csr[o] = i; g_cnt[i] = o + 1; }
}
__global__ void k_scatter(const int* __restrict__ ei) {
    int e = blockIdx.x * blockDim.x + threadIdx.x;
    if (e < EE) {
        int s = ei[e], d = ei[EE + e];
        int p = atomicAdd(&g_cnt[d], 1);
        g_csr[p] = s;
    }
}

// ---------------- kernel 4: layer-1 aggregation + elu + fused layer-2 prep ----------------
// warp per dest node. lane covers 8 output cols (cols lane*8..+7, head = lane>>2).
// Single pass (no max shift; logits are O(10) so exp is safe).
__global__ void __launch_bounds__(256) k_agg1(const float* __restrict__ b1,
                                              const float* __restrict__ W2,
                                              const float* __restrict__ as2,
                                              const float* __restrict__ ad2) {
    int d = (blockIdx.x * blockDim.x + threadIdx.x) >> 5;
    int lane = threadIdx.x & 31;
    if (d >= NN) return;
    int beg = g_off[d], end = g_off[d + 1];
    int myHead = lane >> 2;

    float adh = (lane < 8) ? g_ad1[d * 8 + lane] : 0.f;

    float acc[8];
#pragma unroll
    for (int j = 0; j < 8; j++) acc[j] = 0.f;
    float z = 0.f;

    for (int base = beg; base < end; base += 32) {
        int cnt = min(32, end - base);
        int sv = (base + lane < end) ? g_csr[base + lane] : 0;
        for (int j = 0; j < cnt; j++) {
            int s = __shfl_sync(~0u, sv, j);
            float ea = 0.f;
            if (lane < 8) {
                float a = g_as1[s * 8 + lane] + adh;
                a = a > 0.f ? a : 0.2f * a;
                ea = __expf(a);
                z += ea;
            }
            float eah = __shfl_sync(~0u, ea, myHead);
            uint4 hv = *(const uint4*)&g_h1h[(size_t)s * C1 + lane * 8];
            __half2* hh = (__half2*)&hv;
#pragma unroll
            for (int q = 0; q < 4; q++) {
                float2 f = __half22float2(hh[q]);
                acc[2 * q]     += eah * f.x;
                acc[2 * q + 1] += eah * f.y;
            }
        }
    }
    float zh = __shfl_sync(~0u, z, myHead) + 1e-16f;
    float inv = 1.f / zh;

    // x1 (this lane's 8 cols), elu
    float x1[8];
    float4 bA = *(const float4*)&b1[lane * 8];
    float4 bB = *(const float4*)&b1[lane * 8 + 4];
    float bb[8] = {bA.x, bA.y, bA.z, bA.w, bB.x, bB.y, bB.z, bB.w};
#pragma unroll
    for (int j = 0; j < 8; j++) {
        float v = acc[j] * inv + bb[j];
        x1[j] = v > 0.f ? v : expm1f(v);
    }

    // fused layer-2: h2 = x1 @ W2 (each lane holds cols lane*8..+7 of x1)
    float p[8];
#pragma unroll
    for (int o = 0; o < 8; o++) p[o] = 0.f;
#pragma unroll
    for (int j = 0; j < 8; j++) {
        int c = lane * 8 + j;
        float4 w0 = *(const float4*)&W2[c * 8];
        float4 w1 = *(const float4*)&W2[c * 8 + 4];
        p[0] += x1[j] * w0.x; p[1] += x1[j] * w0.y;
        p[2] += x1[j] * w0.z; p[3] += x1[j] * w0.w;
        p[4] += x1[j] * w1.x; p[5] += x1[j] * w1.y;
        p[6] += x1[j] * w1.z; p[7] += x1[j] * w1.w;
    }
#pragma unroll
    for (int o = 0; o < 8; o++)
#pragma unroll
        for (int k = 16; k > 0; k >>= 1) p[o] += __shfl_xor_sync(~0u, p[o], k);

    float s2 = 0.f, d2 = 0.f;
#pragma unroll
    for (int o = 0; o < 8; o++) { s2 += p[o] * as2[o]; d2 += p[o] * ad2[o]; }
    if (lane == 0) {
        g_a2s[d] = s2; g_a2d[d] = d2;
        *(float4*)&g_h2[d * 8]     = make_float4(p[0], p[1], p[2], p[3]);
        *(float4*)&g_h2[d * 8 + 4] = make_float4(p[4], p[5], p[6], p[7]);
    }
}

// ---------------- kernel 5: layer-2 aggregation + log_softmax (single pass) ----------------
__global__ void __launch_bounds__(256) k_agg2(const float* __restrict__ b2,
                                              float* __restrict__ out) {
    int d = (blockIdx.x * blockDim.x + threadIdx.x) >> 5;
    int lane = threadIdx.x & 31;
    if (d >= NN) return;
    int beg = g_off[d], end = g_off[d + 1];
    float adv = g_a2d[d];

    float z = 0.f, acc[8];
#pragma unroll
    for (int o = 0; o < 8; o++) acc[o] = 0.f;
    for (int e = beg + lane; e < end; e += 32) {
        int s = g_csr[e];
        float a = g_a2s[s] + adv;
        a = a > 0.f ? a : 0.2f * a;
        float ea = __expf(a);
        z += ea;
        const float4* hp = (const float4*)&g_h2[s * 8];
        float4 v0 = hp[0], v1 = hp[1];
        acc[0] += ea * v0.x; acc[1] += ea * v0.y; acc[2] += ea * v0.z; acc[3] += ea * v0.w;
        acc[4] += ea * v1.x; acc[5] += ea * v1.y; acc[6] += ea * v1.z; acc[7] += ea * v1.w;
    }
#pragma unroll
    for (int k = 16; k > 0; k >>= 1) z += __shfl_xor_sync(~0u, z, k);
#pragma unroll
    for (int o = 0; o < 8; o++)
#pragma unroll
        for (int k = 16; k > 0; k >>= 1) acc[o] += __shfl_xor_sync(~0u, acc[o], k);

    float inv = 1.f / (z + 1e-16f);
    float v[8], mx = -1e30f;
#pragma unroll
    for (int o = 0; o < 8; o++) { v[o] = acc[o] * inv + b2[o]; mx = fmaxf(mx, v[o]); }
    float se = 0.f;
#pragma unroll
    for (int o = 0; o < 8; o++) se += expf(v[o] - mx);
    float lse = mx + logf(se);
    if (lane == 0) {
        *(float4*)&out[d * 8]     = make_float4(v[0] - lse, v[1] - lse, v[2] - lse, v[3] - lse);
        *(float4*)&out[d * 8 + 4] = make_float4(v[4] - lse, v[5] - lse, v[6] - lse, v[7] - lse);
    }
}

// ---------------- launch ----------------
extern "C" void kernel_launch(void* const* d_in, const int* in_sizes, int n_in,
                              void* d_out, int out_size) {
    const float* high  = (const float*)d_in[0];
    const float* low   = (const float*)d_in[1];
    const int*   ei    = (const int*)d_in[2];
    const float* Wemb  = (const float*)d_in[3];
    const float* bemb  = (const float*)d_in[4];
    const float* W1    = (const float*)d_in[5];
    const float* asrc1 = (const float*)d_in[6];
    const float* adst1 = (const float*)d_in[7];
    const float* b1    = (const float*)d_in[8];
    const float* W2    = (const float*)d_in[9];
    const float* as2   = (const float*)d_in[10];
    const float* ad2   = (const float*)d_in[11];
    const float* b2    = (const float*)d_in[12];
    float* out = (float*)d_out;

    dim3 eb(192, 2);
    k_emb<<<NN / 2, eb>>>(high, low, Wemb, bemb);

    dim3 gg((NN + 127) / 128, C1 / 128);
    k_gemm<<<gg, 128>>>(W1);

    k_att1<<<(NN + 7) / 8, 256>>>(asrc1, adst1);

    k_cnt_init<<<(NN + 255) / 256, 256>>>();
    k_cnt_edges<<<(EE + 255) / 256, 256>>>(ei);
    k_scan<<<1, 1024>>>();
    k_selfloop<<<(NN + 255) / 256, 256>>>();
    k_scatter<<<(EE + 255) / 256, 256>>>(ei);

    k_agg1<<<(NN + 7) / 8, 256>>>(b1, W2, as2, ad2);
    k_agg2<<<(NN + 7) / 8, 256>>>(b2, out);
}